// round 13
// baseline (speedup 1.0000x reference)
#include <cuda_runtime.h>
#include <cooperative_groups.h>
#include <math.h>

namespace cg = cooperative_groups;

#define Bc 64
#define Sc 2048
#define Hc 512
#define Kc 1024
#define SCC 8              // context CTAs per b == cluster size
#define SCHUNK (Sc/SCC)    // 256 rows per context CTA
#define CTHREADS 512
#define QB 16              // query rows per qproj CTA

// Scratch (no allocations allowed in kernel_launch)
__device__ float g_q[Bc*Hc];            // 128 KB
__device__ float g_scores[Bc*Sc];       // 512 KB

// tanh(x) = 1 - 2/(exp(2x)+1); __expf ~2ulp -> overall ~1e-6 error.
__device__ __forceinline__ float fast_tanhf(float x) {
    float e = __expf(2.0f * x);
    return 1.0f - __fdividef(2.0f, e + 1.0f);
}

#if defined(__CUDA_ARCH__) && (__CUDA_ARCH__ >= 900)
#define GRID_DEP_SYNC() cudaGridDependencySynchronize()
#else
#define GRID_DEP_SYNC()
#endif

// ---------------------------------------------------------------------------
// K1: q[b,h] = sum_e query[b,e] * W_q[h,e]
// grid (Hc/8, Bc/QB) = (64, 4), block 256 (warp per h, QB=16 b's per warp).
// ILP version: 16 register accumulators, e-loop outer (no serial chains),
// one batched 5-step butterfly for all 16 reductions, parallel writeback.
// ---------------------------------------------------------------------------
__global__ void qproj_kernel(const float* __restrict__ query,
                             const float* __restrict__ Wq) {
    __shared__ float4 sq4[QB][Hc/4];        // 32 KB
    const int t = threadIdx.x;
    const int warp = t >> 5, lane = t & 31;
    const int h  = blockIdx.x * 8 + warp;
    const int b0 = blockIdx.y * QB;

    const float4* wrow = (const float4*)(Wq + (size_t)h * Hc);
    float4 w0 = wrow[lane];
    float4 w1 = wrow[lane + 32];
    float4 w2 = wrow[lane + 64];
    float4 w3 = wrow[lane + 96];

    {
        const float4* qsrc = (const float4*)(query + (size_t)b0 * Hc);
        float4* qdst = &sq4[0][0];
#pragma unroll
        for (int j = 0; j < (QB*Hc/4)/256; j++)
            qdst[t + 256*j] = qsrc[t + 256*j];
    }
    __syncthreads();

    float acc[QB];
#pragma unroll
    for (int bb = 0; bb < QB; bb++) acc[bb] = 0.0f;

#pragma unroll
    for (int i = 0; i < 4; i++) {
        float4 w = (i == 0) ? w0 : (i == 1) ? w1 : (i == 2) ? w2 : w3;
#pragma unroll
        for (int bb = 0; bb < QB; bb++) {
            float4 qv = sq4[bb][lane + 32*i];   // LDS.128, independent
            acc[bb] = fmaf(w.x, qv.x, acc[bb]);
            acc[bb] = fmaf(w.y, qv.y, acc[bb]);
            acc[bb] = fmaf(w.z, qv.z, acc[bb]);
            acc[bb] = fmaf(w.w, qv.w, acc[bb]);
        }
    }

    // batched butterfly: 16 independent reductions per step (full ILP)
#pragma unroll
    for (int o = 16; o; o >>= 1) {
#pragma unroll
        for (int bb = 0; bb < QB; bb++)
            acc[bb] += __shfl_xor_sync(0xffffffffu, acc[bb], o);
    }
    // every lane now holds all 16 sums; lane bb writes output bb
    if (lane < QB) g_q[(b0 + lane)*Hc + h] = acc[lane];
}

// ---------------------------------------------------------------------------
// K2: scores[b,s] = sum_h tanh(q[b,h] + pk[b,s,h]) * v[h]
// block 256 (8 warps), warp handles 2 rows -> 16 rows/block, 8192 blocks.
// ---------------------------------------------------------------------------
__global__ void score_kernel(const float* __restrict__ pk,
                             const float* __restrict__ v) {
    __shared__ float sq[Hc];
    __shared__ float sv[Hc];
    const int t = threadIdx.x;
    const int row0 = blockIdx.x * 16;
    const int b = row0 >> 11;               // blocks don't straddle b
    sv[t]       = v[t];                     // input: no dependency
    sv[t + 256] = v[t + 256];
    GRID_DEP_SYNC();                        // wait for qproj's g_q
    sq[t]       = g_q[b*Hc + t];
    sq[t + 256] = g_q[b*Hc + t + 256];
    __syncthreads();

    const int warp = t >> 5, lane = t & 31;
    const int rowA = row0 + warp*2;
    const int rowB = rowA + 1;
    const float4* pA = (const float4*)(pk + (size_t)rowA * Hc);
    const float4* pB = (const float4*)(pk + (size_t)rowB * Hc);
    float accA = 0.0f, accB = 0.0f;
#pragma unroll
    for (int i = 0; i < 4; i++) {
        float4 a = pA[lane + 32*i];
        float4 c = pB[lane + 32*i];
        int e = (lane + 32*i) * 4;
        float q0 = sq[e], q1 = sq[e+1], q2 = sq[e+2], q3 = sq[e+3];
        float v0 = sv[e], v1 = sv[e+1], v2 = sv[e+2], v3 = sv[e+3];
        accA = fmaf(fast_tanhf(a.x + q0), v0, accA);
        accA = fmaf(fast_tanhf(a.y + q1), v1, accA);
        accA = fmaf(fast_tanhf(a.z + q2), v2, accA);
        accA = fmaf(fast_tanhf(a.w + q3), v3, accA);
        accB = fmaf(fast_tanhf(c.x + q0), v0, accB);
        accB = fmaf(fast_tanhf(c.y + q1), v1, accB);
        accB = fmaf(fast_tanhf(c.z + q2), v2, accB);
        accB = fmaf(fast_tanhf(c.w + q3), v3, accB);
    }
#pragma unroll
    for (int o = 16; o; o >>= 1) {
        accA += __shfl_xor_sync(0xffffffffu, accA, o);
        accB += __shfl_xor_sync(0xffffffffu, accB, o);
    }
    if (lane == 0) {
        g_scores[rowA] = accA;
        g_scores[rowB] = accB;
    }
}

// ---------------------------------------------------------------------------
// K3: masked softmax over s for each b. grid Bc, block 256, 8 values/thread.
// ---------------------------------------------------------------------------
__global__ void softmax_kernel(const int* __restrict__ mask,
                               float* __restrict__ alphas_out) {
    const int b = blockIdx.x, t = threadIdx.x;
    __shared__ float red[8];

    int m[8];
#pragma unroll
    for (int i = 0; i < 8; i++) m[i] = mask[b*Sc + t + 256*i];

    GRID_DEP_SYNC();                        // wait for g_scores

    float vals[8];
    float mx = -INFINITY;
#pragma unroll
    for (int i = 0; i < 8; i++) {
        float x = g_scores[b*Sc + t + 256*i];
        if (m[i] == 0) x = -INFINITY;
        vals[i] = x;
        mx = fmaxf(mx, x);
    }
#pragma unroll
    for (int o = 16; o; o >>= 1) mx = fmaxf(mx, __shfl_xor_sync(0xffffffffu, mx, o));
    if ((t & 31) == 0) red[t >> 5] = mx;
    __syncthreads();
    mx = red[0];
#pragma unroll
    for (int i = 1; i < 8; i++) mx = fmaxf(mx, red[i]);

    float sum = 0.0f;
#pragma unroll
    for (int i = 0; i < 8; i++) {
        float e = __expf(vals[i] - mx);
        vals[i] = e;
        sum += e;
    }
#pragma unroll
    for (int o = 16; o; o >>= 1) sum += __shfl_xor_sync(0xffffffffu, sum, o);
    __syncthreads();
    if ((t & 31) == 0) red[t >> 5] = sum;
    __syncthreads();
    float tot = red[0];
#pragma unroll
    for (int i = 1; i < 8; i++) tot += red[i];
    float inv = 1.0f / tot;
#pragma unroll
    for (int i = 0; i < 8; i++)
        alphas_out[b*Sc + t + 256*i] = vals[i] * inv;
}

// ---------------------------------------------------------------------------
// K4: context with in-cluster reduction. grid (SCC, Bc) = (8, 64), 512 thr,
// cluster (8,1,1) = one cluster per b. Same as R11 (best variant).
// ---------------------------------------------------------------------------
__global__ void __cluster_dims__(SCC, 1, 1)
context_cluster_kernel(const float* __restrict__ eh,
                       const float* __restrict__ alphas,
                       float* __restrict__ ctx_out) {
    __shared__ float  sa[SCHUNK];           // 1 KB
    __shared__ float4 shalf[Kc/4];          // 4 KB
    __shared__ float4 spart[Kc/4];          // 4 KB
    cg::cluster_group cl = cg::this_cluster();
    const int c = blockIdx.x;               // == cluster rank
    const int b = blockIdx.y;
    const int t = threadIdx.x;
    const int slot = t & 255;
    const int half = t >> 8;                // 0 or 1

    GRID_DEP_SYNC();                        // wait for alphas (softmax output)
    if (t < SCHUNK) sa[t] = alphas[b*Sc + c*SCHUNK + t];
    __syncthreads();

    const float4* base =
        (const float4*)(eh + ((size_t)(b*Sc + c*SCHUNK + half*128)) * Kc) + slot;
    const float* sah = sa + half*128;
    float4 acc = make_float4(0.f, 0.f, 0.f, 0.f);
#pragma unroll 8
    for (int s = 0; s < 128; s++) {
        float a = sah[s];
        float4 vv = base[(size_t)s * (Kc/4)];
        acc.x = fmaf(a, vv.x, acc.x);
        acc.y = fmaf(a, vv.y, acc.y);
        acc.z = fmaf(a, vv.z, acc.z);
        acc.w = fmaf(a, vv.w, acc.w);
    }

    // combine the two s-halves (fixed order: half0 + half1)
    if (half == 1) shalf[slot] = acc;
    __syncthreads();
    if (half == 0) {
        float4 o = shalf[slot];
        acc.x += o.x; acc.y += o.y; acc.z += o.z; acc.w += o.w;
        spart[slot] = acc;
    }
    cl.sync();                              // all partials visible cluster-wide

    // 8-rank DSMEM reduction: threads 0..255, 8 threads per slot
    if (t < 256) {
        const int myslot = c*32 + (t >> 3); // this CTA's 32-slot stripe
        const int src    = t & 7;           // source rank
        const float4* rp = cl.map_shared_rank(spart, src);
        float4 v = rp[myslot];
#pragma unroll
        for (int o = 4; o; o >>= 1) {       // reduce within 8-lane segments
            v.x += __shfl_down_sync(0xffffffffu, v.x, o, 8);
            v.y += __shfl_down_sync(0xffffffffu, v.y, o, 8);
            v.z += __shfl_down_sync(0xffffffffu, v.z, o, 8);
            v.w += __shfl_down_sync(0xffffffffu, v.w, o, 8);
        }
        if (src == 0)
            ((float4*)ctx_out)[(size_t)b * (Kc/4) + myslot] = v;
    }
    cl.sync();                              // peers done reading our smem
}

// ---------------------------------------------------------------------------
template <typename K, typename... Args>
static inline void launch_pdl(K kernel, dim3 grid, dim3 block, Args... args) {
    cudaLaunchAttribute attr[1];
    attr[0].id = cudaLaunchAttributeProgrammaticStreamSerialization;
    attr[0].val.programmaticStreamSerializationAllowed = 1;
    cudaLaunchConfig_t cfg;
    cfg.gridDim = grid;
    cfg.blockDim = block;
    cfg.dynamicSmemBytes = 0;
    cfg.stream = 0;
    cfg.attrs = attr;
    cfg.numAttrs = 1;
    cudaLaunchKernelEx(&cfg, kernel, args...);
}

extern "C" void kernel_launch(void* const* d_in, const int* in_sizes, int n_in,
                              void* d_out, int out_size) {
    const float* query    = (const float*)d_in[0]; // (B,1,H)
    const float* proj_key = (const float*)d_in[1]; // (B,S,H)
    const float* enc      = (const float*)d_in[2]; // (B,S,K)
    const int*   mask     = (const int*)  d_in[3]; // (B,1,S)
    const float* Wq       = (const float*)d_in[4]; // (H,H)
    const float* v        = (const float*)d_in[5]; // (H,)

    float* ctx    = (float*)d_out;              // (B,1,K)
    float* alphas = (float*)d_out + Bc*Kc;      // (B,1,S)

    qproj_kernel<<<dim3(Hc/8, Bc/QB), 256>>>(query, Wq);
    launch_pdl(score_kernel,           dim3((Bc*Sc)/16), dim3(256), proj_key, v);
    launch_pdl(softmax_kernel,         dim3(Bc),         dim3(256), mask, alphas);
    launch_pdl(context_cluster_kernel, dim3(SCC, Bc),    dim3(CTHREADS), enc,
               (const float*)alphas, ctx);
}

// round 14
// speedup vs baseline: 1.0090x; 1.0090x over previous
#include <cuda_runtime.h>
#include <cooperative_groups.h>
#include <math.h>

namespace cg = cooperative_groups;

#define Bc 64
#define Sc 2048
#define Hc 512
#define Kc 1024
#define SCC 8              // context CTAs per b == cluster size
#define SCHUNK (Sc/SCC)    // 256 rows per context CTA
#define CTHREADS 512
#define QB 16              // query rows per qproj CTA

// Scratch (no allocations allowed in kernel_launch)
__device__ float g_q[Bc*Hc];            // 128 KB
__device__ float g_scores[Bc*Sc];       // 512 KB

// tanh(x) = 1 - 2/(exp(2x)+1); __expf ~2ulp -> overall ~1e-6 error.
__device__ __forceinline__ float fast_tanhf(float x) {
    float e = __expf(2.0f * x);
    return 1.0f - __fdividef(2.0f, e + 1.0f);
}

#if defined(__CUDA_ARCH__) && (__CUDA_ARCH__ >= 900)
#define GRID_DEP_SYNC() cudaGridDependencySynchronize()
#else
#define GRID_DEP_SYNC()
#endif

// ---------------------------------------------------------------------------
// K1: q[b,h] = sum_e query[b,e] * W_q[h,e]
// grid (Hc/8, Bc/QB) = (64, 4), block 256 (warp per h, QB=16 b's per warp).
// 16 register accumulators (all indices compile-time -> registers), batched
// 5-step butterfly, writeback via predicated SELECT chain (no dynamic
// register indexing -> no local-memory spill).
// ---------------------------------------------------------------------------
__global__ void qproj_kernel(const float* __restrict__ query,
                             const float* __restrict__ Wq) {
    __shared__ float4 sq4[QB][Hc/4];        // 32 KB
    const int t = threadIdx.x;
    const int warp = t >> 5, lane = t & 31;
    const int h  = blockIdx.x * 8 + warp;
    const int b0 = blockIdx.y * QB;

    const float4* wrow = (const float4*)(Wq + (size_t)h * Hc);
    float4 w0 = wrow[lane];
    float4 w1 = wrow[lane + 32];
    float4 w2 = wrow[lane + 64];
    float4 w3 = wrow[lane + 96];

    {
        const float4* qsrc = (const float4*)(query + (size_t)b0 * Hc);
        float4* qdst = &sq4[0][0];
#pragma unroll
        for (int j = 0; j < (QB*Hc/4)/256; j++)
            qdst[t + 256*j] = qsrc[t + 256*j];
    }
    __syncthreads();

    float acc[QB];
#pragma unroll
    for (int bb = 0; bb < QB; bb++) acc[bb] = 0.0f;

#pragma unroll
    for (int i = 0; i < 4; i++) {
        float4 w = (i == 0) ? w0 : (i == 1) ? w1 : (i == 2) ? w2 : w3;
#pragma unroll
        for (int bb = 0; bb < QB; bb++) {
            float4 qv = sq4[bb][lane + 32*i];   // LDS.128, independent
            acc[bb] = fmaf(w.x, qv.x, acc[bb]);
            acc[bb] = fmaf(w.y, qv.y, acc[bb]);
            acc[bb] = fmaf(w.z, qv.z, acc[bb]);
            acc[bb] = fmaf(w.w, qv.w, acc[bb]);
        }
    }

    // batched butterfly: 16 independent reductions per step (full ILP)
#pragma unroll
    for (int o = 16; o; o >>= 1) {
#pragma unroll
        for (int bb = 0; bb < QB; bb++)
            acc[bb] += __shfl_xor_sync(0xffffffffu, acc[bb], o);
    }
    // all lanes hold all 16 sums; SELECT chain keeps acc[] in registers
    float out = acc[0];
#pragma unroll
    for (int bb = 1; bb < QB; bb++)
        out = (lane == bb) ? acc[bb] : out;
    if (lane < QB) g_q[(b0 + lane)*Hc + h] = out;
}

// ---------------------------------------------------------------------------
// K2: scores[b,s] = sum_h tanh(q[b,h] + pk[b,s,h]) * v[h]
// block 256 (8 warps), warp handles 2 rows -> 16 rows/block, 8192 blocks.
// ---------------------------------------------------------------------------
__global__ void score_kernel(const float* __restrict__ pk,
                             const float* __restrict__ v) {
    __shared__ float sq[Hc];
    __shared__ float sv[Hc];
    const int t = threadIdx.x;
    const int row0 = blockIdx.x * 16;
    const int b = row0 >> 11;               // blocks don't straddle b
    sv[t]       = v[t];                     // input: no dependency
    sv[t + 256] = v[t + 256];
    GRID_DEP_SYNC();                        // wait for qproj's g_q
    sq[t]       = g_q[b*Hc + t];
    sq[t + 256] = g_q[b*Hc + t + 256];
    __syncthreads();

    const int warp = t >> 5, lane = t & 31;
    const int rowA = row0 + warp*2;
    const int rowB = rowA + 1;
    const float4* pA = (const float4*)(pk + (size_t)rowA * Hc);
    const float4* pB = (const float4*)(pk + (size_t)rowB * Hc);
    float accA = 0.0f, accB = 0.0f;
#pragma unroll
    for (int i = 0; i < 4; i++) {
        float4 a = pA[lane + 32*i];
        float4 c = pB[lane + 32*i];
        int e = (lane + 32*i) * 4;
        float q0 = sq[e], q1 = sq[e+1], q2 = sq[e+2], q3 = sq[e+3];
        float v0 = sv[e], v1 = sv[e+1], v2 = sv[e+2], v3 = sv[e+3];
        accA = fmaf(fast_tanhf(a.x + q0), v0, accA);
        accA = fmaf(fast_tanhf(a.y + q1), v1, accA);
        accA = fmaf(fast_tanhf(a.z + q2), v2, accA);
        accA = fmaf(fast_tanhf(a.w + q3), v3, accA);
        accB = fmaf(fast_tanhf(c.x + q0), v0, accB);
        accB = fmaf(fast_tanhf(c.y + q1), v1, accB);
        accB = fmaf(fast_tanhf(c.z + q2), v2, accB);
        accB = fmaf(fast_tanhf(c.w + q3), v3, accB);
    }
#pragma unroll
    for (int o = 16; o; o >>= 1) {
        accA += __shfl_xor_sync(0xffffffffu, accA, o);
        accB += __shfl_xor_sync(0xffffffffu, accB, o);
    }
    if (lane == 0) {
        g_scores[rowA] = accA;
        g_scores[rowB] = accB;
    }
}

// ---------------------------------------------------------------------------
// K3: masked softmax over s for each b. grid Bc, block 256, 8 values/thread.
// ---------------------------------------------------------------------------
__global__ void softmax_kernel(const int* __restrict__ mask,
                               float* __restrict__ alphas_out) {
    const int b = blockIdx.x, t = threadIdx.x;
    __shared__ float red[8];

    int m[8];
#pragma unroll
    for (int i = 0; i < 8; i++) m[i] = mask[b*Sc + t + 256*i];

    GRID_DEP_SYNC();                        // wait for g_scores

    float vals[8];
    float mx = -INFINITY;
#pragma unroll
    for (int i = 0; i < 8; i++) {
        float x = g_scores[b*Sc + t + 256*i];
        if (m[i] == 0) x = -INFINITY;
        vals[i] = x;
        mx = fmaxf(mx, x);
    }
#pragma unroll
    for (int o = 16; o; o >>= 1) mx = fmaxf(mx, __shfl_xor_sync(0xffffffffu, mx, o));
    if ((t & 31) == 0) red[t >> 5] = mx;
    __syncthreads();
    mx = red[0];
#pragma unroll
    for (int i = 1; i < 8; i++) mx = fmaxf(mx, red[i]);

    float sum = 0.0f;
#pragma unroll
    for (int i = 0; i < 8; i++) {
        float e = __expf(vals[i] - mx);
        vals[i] = e;
        sum += e;
    }
#pragma unroll
    for (int o = 16; o; o >>= 1) sum += __shfl_xor_sync(0xffffffffu, sum, o);
    __syncthreads();
    if ((t & 31) == 0) red[t >> 5] = sum;
    __syncthreads();
    float tot = red[0];
#pragma unroll
    for (int i = 1; i < 8; i++) tot += red[i];
    float inv = 1.0f / tot;
#pragma unroll
    for (int i = 0; i < 8; i++)
        alphas_out[b*Sc + t + 256*i] = vals[i] * inv;
}

// ---------------------------------------------------------------------------
// K4: context with in-cluster reduction. grid (SCC, Bc) = (8, 64), 512 thr,
// cluster (8,1,1) = one cluster per b. Same as R11 (best variant).
// ---------------------------------------------------------------------------
__global__ void __cluster_dims__(SCC, 1, 1)
context_cluster_kernel(const float* __restrict__ eh,
                       const float* __restrict__ alphas,
                       float* __restrict__ ctx_out) {
    __shared__ float  sa[SCHUNK];           // 1 KB
    __shared__ float4 shalf[Kc/4];          // 4 KB
    __shared__ float4 spart[Kc/4];          // 4 KB
    cg::cluster_group cl = cg::this_cluster();
    const int c = blockIdx.x;               // == cluster rank
    const int b = blockIdx.y;
    const int t = threadIdx.x;
    const int slot = t & 255;
    const int half = t >> 8;                // 0 or 1

    GRID_DEP_SYNC();                        // wait for alphas (softmax output)
    if (t < SCHUNK) sa[t] = alphas[b*Sc + c*SCHUNK + t];
    __syncthreads();

    const float4* base =
        (const float4*)(eh + ((size_t)(b*Sc + c*SCHUNK + half*128)) * Kc) + slot;
    const float* sah = sa + half*128;
    float4 acc = make_float4(0.f, 0.f, 0.f, 0.f);
#pragma unroll 8
    for (int s = 0; s < 128; s++) {
        float a = sah[s];
        float4 vv = base[(size_t)s * (Kc/4)];
        acc.x = fmaf(a, vv.x, acc.x);
        acc.y = fmaf(a, vv.y, acc.y);
        acc.z = fmaf(a, vv.z, acc.z);
        acc.w = fmaf(a, vv.w, acc.w);
    }

    // combine the two s-halves (fixed order: half0 + half1)
    if (half == 1) shalf[slot] = acc;
    __syncthreads();
    if (half == 0) {
        float4 o = shalf[slot];
        acc.x += o.x; acc.y += o.y; acc.z += o.z; acc.w += o.w;
        spart[slot] = acc;
    }
    cl.sync();                              // all partials visible cluster-wide

    // 8-rank DSMEM reduction: threads 0..255, 8 threads per slot
    if (t < 256) {
        const int myslot = c*32 + (t >> 3); // this CTA's 32-slot stripe
        const int src    = t & 7;           // source rank
        const float4* rp = cl.map_shared_rank(spart, src);
        float4 v = rp[myslot];
#pragma unroll
        for (int o = 4; o; o >>= 1) {       // reduce within 8-lane segments
            v.x += __shfl_down_sync(0xffffffffu, v.x, o, 8);
            v.y += __shfl_down_sync(0xffffffffu, v.y, o, 8);
            v.z += __shfl_down_sync(0xffffffffu, v.z, o, 8);
            v.w += __shfl_down_sync(0xffffffffu, v.w, o, 8);
        }
        if (src == 0)
            ((float4*)ctx_out)[(size_t)b * (Kc/4) + myslot] = v;
    }
    cl.sync();                              // peers done reading our smem
}

// ---------------------------------------------------------------------------
template <typename K, typename... Args>
static inline void launch_pdl(K kernel, dim3 grid, dim3 block, Args... args) {
    cudaLaunchAttribute attr[1];
    attr[0].id = cudaLaunchAttributeProgrammaticStreamSerialization;
    attr[0].val.programmaticStreamSerializationAllowed = 1;
    cudaLaunchConfig_t cfg;
    cfg.gridDim = grid;
    cfg.blockDim = block;
    cfg.dynamicSmemBytes = 0;
    cfg.stream = 0;
    cfg.attrs = attr;
    cfg.numAttrs = 1;
    cudaLaunchKernelEx(&cfg, kernel, args...);
}

extern "C" void kernel_launch(void* const* d_in, const int* in_sizes, int n_in,
                              void* d_out, int out_size) {
    const float* query    = (const float*)d_in[0]; // (B,1,H)
    const float* proj_key = (const float*)d_in[1]; // (B,S,H)
    const float* enc      = (const float*)d_in[2]; // (B,S,K)
    const int*   mask     = (const int*)  d_in[3]; // (B,1,S)
    const float* Wq       = (const float*)d_in[4]; // (H,H)
    const float* v        = (const float*)d_in[5]; // (H,)

    float* ctx    = (float*)d_out;              // (B,1,K)
    float* alphas = (float*)d_out + Bc*Kc;      // (B,1,S)

    qproj_kernel<<<dim3(Hc/8, Bc/QB), 256>>>(query, Wq);
    launch_pdl(score_kernel,           dim3((Bc*Sc)/16), dim3(256), proj_key, v);
    launch_pdl(softmax_kernel,         dim3(Bc),         dim3(256), mask, alphas);
    launch_pdl(context_cluster_kernel, dim3(SCC, Bc),    dim3(CTHREADS), enc,
               (const float*)alphas, ctx);
}